// round 7
// baseline (speedup 1.0000x reference)
#include <cuda_runtime.h>

#define Bsz 128
#define Tsz 512
#define Isz 64
#define Hsz 256
#define Gsz 768   // 3*H

// ---- device scratch (no cudaMalloc allowed) --------------------------------
__device__ float    g_gx  [(size_t)Tsz * Bsz * Gsz];  // [t][b][768] gate preactivations
__device__ float    g_h1  [(size_t)Tsz * Bsz * Hsz];  // [t][b][256] layer-0 outputs
__device__ float    g_hbuf[2 * Bsz * Hsz];            // double-buffered hidden state
__device__ unsigned g_cnt [2 * Tsz * 8];              // spin-barrier counters (fallback)

// smem: weights 48x260 (padded), h 16x260 (padded), gx 16x48, kred 3x256
#define SW_STRIDE 260
#define SCAN_SMEM_FLOATS (48*SW_STRIDE + 16*260 + 16*48 + 768)
#define SCAN_SMEM_BYTES  (SCAN_SMEM_FLOATS * 4)   // 72704 B

// ---- zero hidden state (+ optionally barrier counters) ---------------------
__global__ void zero_state(int zero_cnt) {
    const int stride = gridDim.x * blockDim.x;
    const int i0 = blockIdx.x * blockDim.x + threadIdx.x;
    for (int i = i0; i < 2 * Bsz * Hsz; i += stride) g_hbuf[i] = 0.0f;
    if (zero_cnt)
        for (int i = i0; i < 2 * Tsz * 8; i += stride) g_cnt[i] = 0u;
}

// ---- SGEMM (NT): g_gx[m][n] = sum_k Arow(m)[k]*W[n][k] + bias[n] ------------
__global__ __launch_bounds__(256) void sgemm_nt(
    const float* __restrict__ A, const float* __restrict__ W,
    const float* __restrict__ bias, int K, int mode)
{
    __shared__ float As[8][128];
    __shared__ float Ws[8][128];

    const int tid = threadIdx.x;
    const int tx = tid & 15, ty = tid >> 4;
    const int bm = blockIdx.y, bn = blockIdx.x;
    const int rowA = tid >> 1;
    const int kq = (tid & 1) * 4;

    const float* aptr;
    if (mode == 0) aptr = A    + ((size_t)rowA * Tsz + bm) * Isz;
    else           aptr = g_h1 + ((size_t)bm * 128 + rowA) * Hsz;
    const float* wptr = W + ((size_t)bn * 128 + rowA) * K;

    float acc[8][8];
#pragma unroll
    for (int i = 0; i < 8; ++i)
#pragma unroll
        for (int j = 0; j < 8; ++j) acc[i][j] = 0.0f;

    for (int k0 = 0; k0 < K; k0 += 8) {
        const float4 av = *(const float4*)(aptr + k0 + kq);
        const float4 wv = *(const float4*)(wptr + k0 + kq);
        __syncthreads();
        As[kq+0][rowA] = av.x; As[kq+1][rowA] = av.y;
        As[kq+2][rowA] = av.z; As[kq+3][rowA] = av.w;
        Ws[kq+0][rowA] = wv.x; Ws[kq+1][rowA] = wv.y;
        Ws[kq+2][rowA] = wv.z; Ws[kq+3][rowA] = wv.w;
        __syncthreads();
#pragma unroll
        for (int kk = 0; kk < 8; ++kk) {
            float a[8], w[8];
            *(float4*)&a[0] = *(const float4*)&As[kk][ty*4];
            *(float4*)&a[4] = *(const float4*)&As[kk][64 + ty*4];
            *(float4*)&w[0] = *(const float4*)&Ws[kk][tx*4];
            *(float4*)&w[4] = *(const float4*)&Ws[kk][64 + tx*4];
#pragma unroll
            for (int i = 0; i < 8; ++i)
#pragma unroll
                for (int j = 0; j < 8; ++j)
                    acc[i][j] = fmaf(a[i], w[j], acc[i][j]);
        }
    }

    const float4 bv0 = *(const float4*)(bias + bn*128 + tx*4);
    const float4 bv1 = *(const float4*)(bias + bn*128 + 64 + tx*4);
#pragma unroll
    for (int i = 0; i < 8; ++i) {
        const int mloc = (i < 4) ? (ty*4 + i) : (64 + ty*4 + i - 4);
        float* c = g_gx + ((size_t)bm*128 + mloc) * Gsz + bn*128;
        float4 v0 = make_float4(acc[i][0]+bv0.x, acc[i][1]+bv0.y,
                                acc[i][2]+bv0.z, acc[i][3]+bv0.w);
        float4 v1 = make_float4(acc[i][4]+bv1.x, acc[i][5]+bv1.y,
                                acc[i][6]+bv1.z, acc[i][7]+bv1.w);
        *(float4*)(c + tx*4)      = v0;
        *(float4*)(c + 64 + tx*4) = v1;
    }
}

// ---- persistent GRU scan ----------------------------------------------------
// 128 CTAs = 8 batch-groups x 16 hidden-groups; 512 threads; k-split 2.
// Sync per step: cluster barrier (cluster == batch-group) or L2-spin fallback.
__global__ __launch_bounds__(512, 1) void gru_scan(
    const float* __restrict__ Whh, const float* __restrict__ bhh,
    int layer, int write_ys, int use_cluster)
{
    extern __shared__ float sm[];
    float* sw   = sm;                          // [48][SW_STRIDE]
    float* sh   = sm + 48 * SW_STRIDE;         // [16][260]
    float* sgx  = sh + 16 * 260;               // [16][48]
    float* sred = sgx + 16 * 48;               // [3][256]

    const int tid = threadIdx.x;
    const int bg  = blockIdx.x >> 4;           // 0..7
    const int hg  = blockIdx.x & 15;           // 0..15
    const int b0  = bg << 4, j0 = hg << 4;
    const int bl  = tid & 15;
    const int jl  = (tid >> 4) & 15;
    const int kh  = tid >> 8;                  // 0/1 k-half
    const int b   = b0 + bl, j = j0 + jl;

    // weight tile -> smem once (48 rows x 64 float4), padded rows
    for (int idx = tid; idx < 3072; idx += 512) {
        const int row = idx >> 6, k4 = idx & 63;
        const int g = row >> 4, u = row & 15;
        *(float4*)(sw + row * SW_STRIDE + (k4 << 2)) =
            __ldg((const float4*)(Whh + (size_t)((g << 8) + j0 + u) * 256) + k4);
    }
    const float bhr = bhh[j];
    const float bhz = bhh[256 + j];
    const float bhn = bhh[512 + j];
    unsigned* cnt = g_cnt + layer * (Tsz * 8);

    // gx staging role (192 threads, one float4 each)
    const bool gxth = tid < 192;
    const int  seg = tid >> 2, q = tid & 3;
    const int  gbb = seg / 3, gg = seg - gbb * 3;
    const float* gxp = g_gx + (size_t)(b0 + gbb) * Gsz + (gg << 8) + j0 + (q << 2);
    const size_t gxstep = (size_t)128 * Gsz;

    float4 gxa = make_float4(0.f, 0.f, 0.f, 0.f);
    if (gxth) gxa = __ldcg((const float4*)gxp);   // t = 0

    int cur = 0;
    for (int t = 0; t < Tsz; ++t) {
        // stage gx(t) (local smem, no peer dependency); prefetch gx(t+1)
        if (gxth) {
            *(float4*)(sgx + gbb * 48 + (gg << 4) + (q << 2)) = gxa;
            if (t + 1 < Tsz)
                gxa = __ldcg((const float4*)(gxp + (size_t)(t + 1) * gxstep));
        }
        // wait for peers' h(t) stores
        if (t > 0) {
            if (use_cluster) {
                asm volatile("barrier.cluster.wait.aligned;" ::: "memory");
            } else {
                if (tid == 0) {
                    unsigned v;
                    unsigned* c = cnt + ((t - 1) << 3) + bg;
                    do {
                        asm volatile("ld.acquire.gpu.global.u32 %0, [%1];"
                                     : "=r"(v) : "l"(c) : "memory");
                    } while (v < 16u);
                }
                __syncthreads();
            }
        }
        // load h(t) (L2 path; L1 stale across SMs) and land into smem
        float4 hr[2];
        const float* hsrc = g_hbuf + cur * (Bsz * Hsz) + (b0 << 8);
#pragma unroll
        for (int r = 0; r < 2; ++r) {
            const int i = tid + (r << 9);
            hr[r] = __ldcg((const float4*)(hsrc + ((i >> 6) << 8)) + (i & 63));
        }
#pragma unroll
        for (int r = 0; r < 2; ++r) {
            const int i = tid + (r << 9);
            *(float4*)(sh + (i >> 6) * 260 + ((i & 63) << 2)) = hr[r];
        }
        __syncthreads();

        float accr, accz, accn, gxn = 0.f;
        if (kh == 0) {
            accr = sgx[bl*48 + jl]      + bhr;
            accz = sgx[bl*48 + 16 + jl] + bhz;
            gxn  = sgx[bl*48 + 32 + jl];
            accn = bhn;
        } else {
            accr = 0.f; accz = 0.f; accn = 0.f;
        }

        const float4* hv = (const float4*)(sh + bl * 260)             + (kh << 5);
        const float4* wr = (const float4*)(sw + (jl)      * SW_STRIDE) + (kh << 5);
        const float4* wz = (const float4*)(sw + (16 + jl) * SW_STRIDE) + (kh << 5);
        const float4* wn = (const float4*)(sw + (32 + jl) * SW_STRIDE) + (kh << 5);
#pragma unroll 8
        for (int k4 = 0; k4 < 32; ++k4) {
            const float4 h4 = hv[k4];
            const float4 w0 = wr[k4], w1 = wz[k4], w2 = wn[k4];
            accr = fmaf(h4.x, w0.x, accr); accr = fmaf(h4.y, w0.y, accr);
            accr = fmaf(h4.z, w0.z, accr); accr = fmaf(h4.w, w0.w, accr);
            accz = fmaf(h4.x, w1.x, accz); accz = fmaf(h4.y, w1.y, accz);
            accz = fmaf(h4.z, w1.z, accz); accz = fmaf(h4.w, w1.w, accz);
            accn = fmaf(h4.x, w2.x, accn); accn = fmaf(h4.y, w2.y, accn);
            accn = fmaf(h4.z, w2.z, accn); accn = fmaf(h4.w, w2.w, accn);
        }

        // combine k-halves
        if (kh == 1) {
            sred[(jl << 4) + bl]        = accr;
            sred[256 + (jl << 4) + bl]  = accz;
            sred[512 + (jl << 4) + bl]  = accn;
        }
        __syncthreads();
        if (kh == 0) {
            accr += sred[(jl << 4) + bl];
            accz += sred[256 + (jl << 4) + bl];
            accn += sred[512 + (jl << 4) + bl];

            const float r = __fdividef(1.0f, 1.0f + __expf(-accr));
            const float z = __fdividef(1.0f, 1.0f + __expf(-accz));
            const float xn = fmaf(r, accn, gxn);
            // overflow-safe fast tanh: e^{2|x|} -> inf gives n -> 1 (no NaN)
            const float e = __expf(2.0f * fabsf(xn));
            float n = 1.0f - __fdividef(2.0f, e + 1.0f);
            n = copysignf(n, xn);

            const float hold = sh[bl * 260 + j0 + jl];
            const float hnew = fmaf(z, hold - n, n);   // (1-z)*n + z*h

            __stcg(g_hbuf + (cur ^ 1) * (Bsz * Hsz) + (b << 8) + j, hnew);
            if (write_ys)
                g_h1[(size_t)((t << 7) + b) * Hsz + j] = hnew;
        }
        __syncthreads();   // all consumers of sh/sgx done; hnew stores issued

        if (t + 1 < Tsz) {
            if (use_cluster) {
                asm volatile("barrier.cluster.arrive.aligned;" ::: "memory");
            } else {
                if (tid == 0)
                    asm volatile("red.release.gpu.global.add.u32 [%0], 1;"
                                 :: "l"(cnt + (t << 3) + bg) : "memory");
            }
        }
        cur ^= 1;
    }
}

// ---- head: out[b] = W2 . relu(W1 . h_last[b] + b1) + b2 --------------------
__global__ void head_kernel(const float* __restrict__ W1, const float* __restrict__ b1,
                            const float* __restrict__ W2, const float* __restrict__ b2,
                            float* __restrict__ out)
{
    __shared__ float red[128];
    const int b = blockIdx.x, u = threadIdx.x;
    const float* hb = g_hbuf + (b << 8);    // final h in buffer 0 (T even)
    const float* w  = W1 + (size_t)u * 256;

    float acc = b1[u];
#pragma unroll 8
    for (int k4 = 0; k4 < 64; ++k4) {
        const float4 h4 = __ldcg((const float4*)hb + k4);
        const float4 w4 = __ldg((const float4*)w + k4);
        acc = fmaf(h4.x, w4.x, acc); acc = fmaf(h4.y, w4.y, acc);
        acc = fmaf(h4.z, w4.z, acc); acc = fmaf(h4.w, w4.w, acc);
    }
    red[u] = fmaxf(acc, 0.0f) * __ldg(W2 + u);
    __syncthreads();
#pragma unroll
    for (int s = 64; s > 0; s >>= 1) {
        if (u < s) red[u] += red[u + s];
        __syncthreads();
    }
    if (u == 0) out[b] = red[0] + b2[0];
}

// ---- launch sequence (graph-capturable: kernel launches only) --------------
extern "C" void kernel_launch(void* const* d_in, const int* in_sizes, int n_in,
                              void* d_out, int out_size)
{
    const float* x    = (const float*)d_in[0];
    const float* Wih0 = (const float*)d_in[1];
    const float* Whh0 = (const float*)d_in[2];
    const float* bih0 = (const float*)d_in[3];
    const float* bhh0 = (const float*)d_in[4];
    const float* Wih1 = (const float*)d_in[5];
    const float* Whh1 = (const float*)d_in[6];
    const float* bih1 = (const float*)d_in[7];
    const float* bhh1 = (const float*)d_in[8];
    const float* W1   = (const float*)d_in[9];
    const float* b1   = (const float*)d_in[10];
    const float* W2   = (const float*)d_in[11];
    const float* b2   = (const float*)d_in[12];
    float* out = (float*)d_out;

    cudaFuncSetAttribute(gru_scan, cudaFuncAttributeMaxDynamicSharedMemorySize,
                         SCAN_SMEM_BYTES);
    cudaFuncSetAttribute(gru_scan, cudaFuncAttributeNonPortableClusterSizeAllowed, 1);

    // Can we run 16-CTA clusters? (deterministic query, same result every call)
    cudaLaunchConfig_t qcfg = {};
    qcfg.gridDim = dim3(128, 1, 1);
    qcfg.blockDim = dim3(512, 1, 1);
    qcfg.dynamicSmemBytes = SCAN_SMEM_BYTES;
    qcfg.numAttrs = 0;
    int maxClu = 0;
    cudaError_t qerr = cudaOccupancyMaxPotentialClusterSize(&maxClu, gru_scan, &qcfg);
    const int use_cluster = (qerr == cudaSuccess && maxClu >= 16) ? 1 : 0;

    cudaLaunchConfig_t ccfg = qcfg;
    cudaLaunchAttribute cattr[1];
    cattr[0].id = cudaLaunchAttributeClusterDimension;
    cattr[0].val.clusterDim.x = 16;
    cattr[0].val.clusterDim.y = 1;
    cattr[0].val.clusterDim.z = 1;
    ccfg.attrs = cattr;
    ccfg.numAttrs = 1;

    const dim3 ggrid(6, 512);

    // fresh state + spin counters every replay
    zero_state<<<64, 256>>>(1);

    // layer 0
    sgemm_nt<<<ggrid, 256>>>(x, Wih0, bih0, Isz, 0);
    if (use_cluster)
        cudaLaunchKernelEx(&ccfg, gru_scan, Whh0, bhh0, 0, 1, 1);
    else
        gru_scan<<<128, 512, SCAN_SMEM_BYTES>>>(Whh0, bhh0, 0, 1, 0);

    // layer 1 (re-zero hidden state: layer 1 starts from h=0)
    sgemm_nt<<<ggrid, 256>>>(x, Wih1, bih1, Hsz, 1);
    zero_state<<<64, 256>>>(0);
    if (use_cluster)
        cudaLaunchKernelEx(&ccfg, gru_scan, Whh1, bhh1, 1, 0, 1);
    else
        gru_scan<<<128, 512, SCAN_SMEM_BYTES>>>(Whh1, bhh1, 1, 0, 0);

    // head
    head_kernel<<<128, 128>>>(W1, b1, W2, b2, out);
}

// round 8
// speedup vs baseline: 1.7673x; 1.7673x over previous
#include <cuda_runtime.h>

#define Bsz 128
#define Tsz 512
#define Isz 64
#define Hsz 256
#define Gsz 768   // 3*H

// ---- device scratch (no cudaMalloc allowed) --------------------------------
__device__ float    g_gx  [(size_t)Tsz * Bsz * Gsz];  // [t][b][768] gate preactivations
__device__ float    g_h1  [(size_t)Tsz * Bsz * Hsz];  // [t][b][256] layer-0 outputs
__device__ float    g_hbuf[2 * Bsz * Hsz];            // double-buffered hidden state
__device__ unsigned g_cnt [2 * Tsz * 16];             // per layer/step/batch-group barrier

// smem: weights 96x260 (padded), h 8x260 (padded), gx 8x96
#define SW_STRIDE 260
#define SCAN_SMEM_FLOATS (96*SW_STRIDE + 8*260 + 8*96)
#define SCAN_SMEM_BYTES  (SCAN_SMEM_FLOATS * 4)   // 111232 B

// ---- zero hidden state (+ optionally barrier counters) ---------------------
__global__ void zero_state(int zero_cnt) {
    const int stride = gridDim.x * blockDim.x;
    const int i0 = blockIdx.x * blockDim.x + threadIdx.x;
    for (int i = i0; i < 2 * Bsz * Hsz; i += stride) g_hbuf[i] = 0.0f;
    if (zero_cnt)
        for (int i = i0; i < 2 * Tsz * 16; i += stride) g_cnt[i] = 0u;
}

// ---- SGEMM (NT): g_gx[m][n] = sum_k Arow(m)[k]*W[n][k] + bias[n] ------------
// mode 0: Arow(m)=x[(b*T+t)*I], m = t*128+b (bm=t,rowA=b), K=64
// mode 1: Arow(m)=g_h1+m*256, K=256.  Tile 128x128xBK8, 256 thr, 8x8 micro.
__global__ __launch_bounds__(256) void sgemm_nt(
    const float* __restrict__ A, const float* __restrict__ W,
    const float* __restrict__ bias, int K, int mode)
{
    __shared__ float As[8][128];
    __shared__ float Ws[8][128];

    const int tid = threadIdx.x;
    const int tx = tid & 15, ty = tid >> 4;
    const int bm = blockIdx.y, bn = blockIdx.x;
    const int rowA = tid >> 1;
    const int kq = (tid & 1) * 4;

    const float* aptr;
    if (mode == 0) aptr = A    + ((size_t)rowA * Tsz + bm) * Isz;
    else           aptr = g_h1 + ((size_t)bm * 128 + rowA) * Hsz;
    const float* wptr = W + ((size_t)bn * 128 + rowA) * K;

    float acc[8][8];
#pragma unroll
    for (int i = 0; i < 8; ++i)
#pragma unroll
        for (int j = 0; j < 8; ++j) acc[i][j] = 0.0f;

    for (int k0 = 0; k0 < K; k0 += 8) {
        const float4 av = *(const float4*)(aptr + k0 + kq);
        const float4 wv = *(const float4*)(wptr + k0 + kq);
        __syncthreads();
        As[kq+0][rowA] = av.x; As[kq+1][rowA] = av.y;
        As[kq+2][rowA] = av.z; As[kq+3][rowA] = av.w;
        Ws[kq+0][rowA] = wv.x; Ws[kq+1][rowA] = wv.y;
        Ws[kq+2][rowA] = wv.z; Ws[kq+3][rowA] = wv.w;
        __syncthreads();
#pragma unroll
        for (int kk = 0; kk < 8; ++kk) {
            float a[8], w[8];
            *(float4*)&a[0] = *(const float4*)&As[kk][ty*4];
            *(float4*)&a[4] = *(const float4*)&As[kk][64 + ty*4];
            *(float4*)&w[0] = *(const float4*)&Ws[kk][tx*4];
            *(float4*)&w[4] = *(const float4*)&Ws[kk][64 + tx*4];
#pragma unroll
            for (int i = 0; i < 8; ++i)
#pragma unroll
                for (int j = 0; j < 8; ++j)
                    acc[i][j] = fmaf(a[i], w[j], acc[i][j]);
        }
    }

    const float4 bv0 = *(const float4*)(bias + bn*128 + tx*4);
    const float4 bv1 = *(const float4*)(bias + bn*128 + 64 + tx*4);
#pragma unroll
    for (int i = 0; i < 8; ++i) {
        const int mloc = (i < 4) ? (ty*4 + i) : (64 + ty*4 + i - 4);
        float* c = g_gx + ((size_t)bm*128 + mloc) * Gsz + bn*128;
        float4 v0 = make_float4(acc[i][0]+bv0.x, acc[i][1]+bv0.y,
                                acc[i][2]+bv0.z, acc[i][3]+bv0.w);
        float4 v1 = make_float4(acc[i][4]+bv1.x, acc[i][5]+bv1.y,
                                acc[i][6]+bv1.z, acc[i][7]+bv1.w);
        *(float4*)(c + tx*4)      = v0;
        *(float4*)(c + 64 + tx*4) = v1;
    }
}

// ---- persistent GRU scan ----------------------------------------------------
// 128 CTAs = 16 batch-groups x 8 hidden-groups; 256 threads.
// Tile per CTA: 8 batches x 32 hidden x 3 gates. Sync domain = 8 CTAs.
__global__ __launch_bounds__(256, 1) void gru_scan(
    const float* __restrict__ Whh, const float* __restrict__ bhh,
    int layer, int write_ys)
{
    extern __shared__ float sm[];
    float* sw  = sm;                        // [96][SW_STRIDE] rows = g*32+u
    float* sh  = sm + 96 * SW_STRIDE;       // [8][260] current h
    float* sgx = sh + 8 * 260;              // [8][96]  gx stage (b, g*32+jl)

    const int tid = threadIdx.x;
    const int bg  = blockIdx.x >> 3;        // 0..15
    const int hg  = blockIdx.x & 7;         // 0..7
    const int b0  = bg << 3, j0 = hg << 5;
    const int bl  = tid & 7;                // 0..7
    const int jl  = tid >> 3;               // 0..31
    const int b   = b0 + bl,  j = j0 + jl;

    // weight tile -> smem once (96 rows x 64 float4), padded rows
    for (int idx = tid; idx < 6144; idx += 256) {
        const int row = idx >> 6, k4 = idx & 63;
        const int g = row >> 5, u = row & 31;
        *(float4*)(sw + row * SW_STRIDE + (k4 << 2)) =
            __ldg((const float4*)(Whh + (size_t)((g << 8) + j0 + u) * 256) + k4);
    }
    const float bhr = bhh[j];
    const float bhz = bhh[256 + j];
    const float bhn = bhh[512 + j];
    unsigned* cnt = g_cnt + layer * (Tsz * 16);

    // gx staging role (192 threads, one float4 each): tile = 8b x 3g x 32j
    const bool gxth = tid < 192;
    const int  seg = tid >> 3, q = tid & 7;   // seg 0..23, q 0..7
    const int  gbb = seg / 3, gg = seg - gbb * 3;
    const float* gxp = g_gx + (size_t)(b0 + gbb) * Gsz + (gg << 8) + j0 + (q << 2);
    const size_t gxstep = (size_t)128 * Gsz;

    float4 gxa = make_float4(0.f, 0.f, 0.f, 0.f);
    if (gxth) gxa = __ldcg((const float4*)gxp);   // t = 0

    int cur = 0;
    for (int t = 0; t < Tsz; ++t) {
        // stage gx(t) (local, no peer dependency); prefetch gx(t+1)
        if (gxth) {
            *(float4*)(sgx + gbb * 96 + (gg << 5) + (q << 2)) = gxa;
            if (t + 1 < Tsz)
                gxa = __ldcg((const float4*)(gxp + (size_t)(t + 1) * gxstep));
        }
        // wait for peers' h(t) stores: every thread acquires, no block barrier
        if (t > 0) {
            const unsigned* c = cnt + ((t - 1) << 4) + bg;
            unsigned v;
            do {
                asm volatile("ld.acquire.gpu.global.u32 %0, [%1];"
                             : "=r"(v) : "l"(c) : "memory");
            } while (v < 8u);
        }
        // load h(t): 8 rows x 256 = 512 float4, 2 per thread (L2 path)
        {
            const float* hsrc = g_hbuf + cur * (Bsz * Hsz) + (b0 << 8);
            float4 h0 = __ldcg((const float4*)(hsrc + ((tid >> 6) << 8)) + (tid & 63));
            const int i1 = tid + 256;
            float4 h1 = __ldcg((const float4*)(hsrc + ((i1 >> 6) << 8)) + (i1 & 63));
            *(float4*)(sh + (tid >> 6) * 260 + ((tid & 63) << 2)) = h0;
            *(float4*)(sh + (i1 >> 6) * 260 + ((i1 & 63) << 2)) = h1;
        }
        __syncthreads();

        float accr = sgx[bl*96 + jl]      + bhr;
        float accz = sgx[bl*96 + 32 + jl] + bhz;
        const float gxn = sgx[bl*96 + 64 + jl];
        float accn = bhn;

        const float4* hv = (const float4*)(sh + bl * 260);
        const float4* wr = (const float4*)(sw + (jl)      * SW_STRIDE);
        const float4* wz = (const float4*)(sw + (32 + jl) * SW_STRIDE);
        const float4* wn = (const float4*)(sw + (64 + jl) * SW_STRIDE);
#pragma unroll 8
        for (int k4 = 0; k4 < 64; ++k4) {
            const float4 h4 = hv[k4];
            const float4 w0 = wr[k4], w1 = wz[k4], w2 = wn[k4];
            accr = fmaf(h4.x, w0.x, accr); accr = fmaf(h4.y, w0.y, accr);
            accr = fmaf(h4.z, w0.z, accr); accr = fmaf(h4.w, w0.w, accr);
            accz = fmaf(h4.x, w1.x, accz); accz = fmaf(h4.y, w1.y, accz);
            accz = fmaf(h4.z, w1.z, accz); accz = fmaf(h4.w, w1.w, accz);
            accn = fmaf(h4.x, w2.x, accn); accn = fmaf(h4.y, w2.y, accn);
            accn = fmaf(h4.z, w2.z, accn); accn = fmaf(h4.w, w2.w, accn);
        }

        // fast gates (MUFU): sigmoid + overflow-safe tanh
        const float r = __fdividef(1.0f, 1.0f + __expf(-accr));
        const float z = __fdividef(1.0f, 1.0f + __expf(-accz));
        const float xn = fmaf(r, accn, gxn);
        const float e = __expf(2.0f * fabsf(xn));
        float n = 1.0f - __fdividef(2.0f, e + 1.0f);
        n = copysignf(n, xn);

        const float hold = sh[bl * 260 + j0 + jl];
        const float hnew = fmaf(z, hold - n, n);   // (1-z)*n + z*h

        __stcg(g_hbuf + (cur ^ 1) * (Bsz * Hsz) + (b << 8) + j, hnew);
        if (write_ys)
            g_h1[(size_t)((t << 7) + b) * Hsz + j] = hnew;

        __syncthreads();   // all sh/sgx reads done, all hnew stores issued
        if (t + 1 < Tsz && tid == 0) {
            // release-arrive: cumulatively orders the CTA's stores (via the
            // block barrier) before the counter increment; no return value
            asm volatile("red.release.gpu.global.add.u32 [%0], 1;"
                         :: "l"(cnt + (t << 4) + bg) : "memory");
        }
        cur ^= 1;
    }
}

// ---- head: out[b] = W2 . relu(W1 . h_last[b] + b1) + b2 --------------------
__global__ void head_kernel(const float* __restrict__ W1, const float* __restrict__ b1,
                            const float* __restrict__ W2, const float* __restrict__ b2,
                            float* __restrict__ out)
{
    __shared__ float red[128];
    const int b = blockIdx.x, u = threadIdx.x;
    const float* hb = g_hbuf + (b << 8);    // final h in buffer 0 (T even)
    const float* w  = W1 + (size_t)u * 256;

    float acc = b1[u];
#pragma unroll 8
    for (int k4 = 0; k4 < 64; ++k4) {
        const float4 h4 = __ldcg((const float4*)hb + k4);
        const float4 w4 = __ldg((const float4*)w + k4);
        acc = fmaf(h4.x, w4.x, acc); acc = fmaf(h4.y, w4.y, acc);
        acc = fmaf(h4.z, w4.z, acc); acc = fmaf(h4.w, w4.w, acc);
    }
    red[u] = fmaxf(acc, 0.0f) * __ldg(W2 + u);
    __syncthreads();
#pragma unroll
    for (int s = 64; s > 0; s >>= 1) {
        if (u < s) red[u] += red[u + s];
        __syncthreads();
    }
    if (u == 0) out[b] = red[0] + b2[0];
}

// ---- launch sequence (graph-capturable: kernel launches only) --------------
extern "C" void kernel_launch(void* const* d_in, const int* in_sizes, int n_in,
                              void* d_out, int out_size)
{
    const float* x    = (const float*)d_in[0];
    const float* Wih0 = (const float*)d_in[1];
    const float* Whh0 = (const float*)d_in[2];
    const float* bih0 = (const float*)d_in[3];
    const float* bhh0 = (const float*)d_in[4];
    const float* Wih1 = (const float*)d_in[5];
    const float* Whh1 = (const float*)d_in[6];
    const float* bih1 = (const float*)d_in[7];
    const float* bhh1 = (const float*)d_in[8];
    const float* W1   = (const float*)d_in[9];
    const float* b1   = (const float*)d_in[10];
    const float* W2   = (const float*)d_in[11];
    const float* b2   = (const float*)d_in[12];
    float* out = (float*)d_out;

    cudaFuncSetAttribute(gru_scan, cudaFuncAttributeMaxDynamicSharedMemorySize,
                         SCAN_SMEM_BYTES);

    const dim3 ggrid(6, 512);

    // fresh state + barrier counters every replay
    zero_state<<<64, 256>>>(1);

    // layer 0
    sgemm_nt<<<ggrid, 256>>>(x, Wih0, bih0, Isz, 0);
    gru_scan<<<128, 256, SCAN_SMEM_BYTES>>>(Whh0, bhh0, 0, 1);

    // layer 1 (re-zero hidden state: layer 1 starts from h=0)
    sgemm_nt<<<ggrid, 256>>>(x, Wih1, bih1, Hsz, 1);
    zero_state<<<64, 256>>>(0);
    gru_scan<<<128, 256, SCAN_SMEM_BYTES>>>(Whh1, bhh1, 1, 0);

    // head
    head_kernel<<<128, 128>>>(W1, b1, W2, b2, out);
}

// round 9
// speedup vs baseline: 2.5321x; 1.4327x over previous
#include <cuda_runtime.h>

#define Bsz 128
#define Tsz 512
#define Isz 64
#define Hsz 256
#define Gsz 768   // 3*H

// ---- device scratch (no cudaMalloc allowed) --------------------------------
__device__ float    g_gx  [(size_t)Tsz * Bsz * Gsz];  // [t][b][768] gate preactivations
__device__ float    g_h1  [(size_t)Tsz * Bsz * Hsz];  // [t][b][256] layer-0 outputs
__device__ float    g_hbuf[2 * Bsz * Hsz];            // double-buffered hidden state
__device__ unsigned g_cnt [2 * Tsz * 16];             // per layer/step/batch-group barrier

// ---- zero hidden state (+ optionally barrier counters) ---------------------
__global__ void zero_state(int zero_cnt) {
    const int stride = gridDim.x * blockDim.x;
    const int i0 = blockIdx.x * blockDim.x + threadIdx.x;
    for (int i = i0; i < 2 * Bsz * Hsz; i += stride) g_hbuf[i] = 0.0f;
    if (zero_cnt)
        for (int i = i0; i < 2 * Tsz * 16; i += stride) g_cnt[i] = 0u;
}

// ---- SGEMM (NT): g_gx[m][n] = sum_k Arow(m)[k]*W[n][k] + bias[n] ------------
// mode 0: Arow(m)=x[(b*T+t)*I], m = t*128+b (bm=t,rowA=b), K=64
// mode 1: Arow(m)=g_h1+m*256, K=256.  Tile 128x128xBK8, 256 thr, 8x8 micro.
__global__ __launch_bounds__(256) void sgemm_nt(
    const float* __restrict__ A, const float* __restrict__ W,
    const float* __restrict__ bias, int K, int mode)
{
    __shared__ float As[8][128];
    __shared__ float Ws[8][128];

    const int tid = threadIdx.x;
    const int tx = tid & 15, ty = tid >> 4;
    const int bm = blockIdx.y, bn = blockIdx.x;
    const int rowA = tid >> 1;
    const int kq = (tid & 1) * 4;

    const float* aptr;
    if (mode == 0) aptr = A    + ((size_t)rowA * Tsz + bm) * Isz;
    else           aptr = g_h1 + ((size_t)bm * 128 + rowA) * Hsz;
    const float* wptr = W + ((size_t)bn * 128 + rowA) * K;

    float acc[8][8];
#pragma unroll
    for (int i = 0; i < 8; ++i)
#pragma unroll
        for (int j = 0; j < 8; ++j) acc[i][j] = 0.0f;

    for (int k0 = 0; k0 < K; k0 += 8) {
        const float4 av = *(const float4*)(aptr + k0 + kq);
        const float4 wv = *(const float4*)(wptr + k0 + kq);
        __syncthreads();
        As[kq+0][rowA] = av.x; As[kq+1][rowA] = av.y;
        As[kq+2][rowA] = av.z; As[kq+3][rowA] = av.w;
        Ws[kq+0][rowA] = wv.x; Ws[kq+1][rowA] = wv.y;
        Ws[kq+2][rowA] = wv.z; Ws[kq+3][rowA] = wv.w;
        __syncthreads();
#pragma unroll
        for (int kk = 0; kk < 8; ++kk) {
            float a[8], w[8];
            *(float4*)&a[0] = *(const float4*)&As[kk][ty*4];
            *(float4*)&a[4] = *(const float4*)&As[kk][64 + ty*4];
            *(float4*)&w[0] = *(const float4*)&Ws[kk][tx*4];
            *(float4*)&w[4] = *(const float4*)&Ws[kk][64 + tx*4];
#pragma unroll
            for (int i = 0; i < 8; ++i)
#pragma unroll
                for (int j = 0; j < 8; ++j)
                    acc[i][j] = fmaf(a[i], w[j], acc[i][j]);
        }
    }

    const float4 bv0 = *(const float4*)(bias + bn*128 + tx*4);
    const float4 bv1 = *(const float4*)(bias + bn*128 + 64 + tx*4);
#pragma unroll
    for (int i = 0; i < 8; ++i) {
        const int mloc = (i < 4) ? (ty*4 + i) : (64 + ty*4 + i - 4);
        float* c = g_gx + ((size_t)bm*128 + mloc) * Gsz + bn*128;
        float4 v0 = make_float4(acc[i][0]+bv0.x, acc[i][1]+bv0.y,
                                acc[i][2]+bv0.z, acc[i][3]+bv0.w);
        float4 v1 = make_float4(acc[i][4]+bv1.x, acc[i][5]+bv1.y,
                                acc[i][6]+bv1.z, acc[i][7]+bv1.w);
        *(float4*)(c + tx*4)      = v0;
        *(float4*)(c + 64 + tx*4) = v1;
    }
}

// ---- persistent GRU scan ----------------------------------------------------
// 128 CTAs = 16 batch-groups x 8 hidden-groups; 256 threads.
// Tile per CTA: 8 batches x 32 hidden x 3 gates. Sync domain = 8 CTAs.
// W_hh tile lives in REGISTERS (w[3][32] per thread, constant across steps).
// h staged transposed in smem -> inner-loop loads are warp-uniform broadcasts.
__global__ __launch_bounds__(256, 1) void gru_scan(
    const float* __restrict__ Whh, const float* __restrict__ bhh,
    int layer, int write_ys)
{
    __shared__ float shT[256 * 9];      // h transposed: [k][b], row pad 9
    __shared__ float sp [8 * 96 * 9];   // partials: [kc][g(96)][b], row pad 9

    const int tid = threadIdx.x;
    const int bg  = blockIdx.x >> 3;    // 0..15
    const int hg  = blockIdx.x & 7;     // 0..7
    const int b0  = bg << 3, j0 = hg << 5;

    // compute mapping: warp-uniform kc, lanes = gc
    const int kc = tid >> 5;            // k-chunk 0..7
    const int gc = tid & 31;            // hidden unit within tile 0..31
    // epilogue mapping
    const int bl = tid >> 5;            // batch 0..7
    const int ge = tid & 31;            // hidden unit 0..31

    // weights -> registers: 3 gate-rows of unit j0+gc, k-chunk kc (96 floats)
    float w[3][32];
#pragma unroll
    for (int gi = 0; gi < 3; ++gi) {
        const float* wrow = Whh + (size_t)(gi * 256 + j0 + gc) * 256 + (kc << 5);
#pragma unroll
        for (int q = 0; q < 8; ++q) {
            float4 v = __ldg((const float4*)wrow + q);
            w[gi][q*4+0] = v.x; w[gi][q*4+1] = v.y;
            w[gi][q*4+2] = v.z; w[gi][q*4+3] = v.w;
        }
    }
    const float bhr = bhh[j0 + ge];
    const float bhz = bhh[256 + j0 + ge];
    const float bhn = bhh[512 + j0 + ge];
    unsigned* cnt = g_cnt + layer * (Tsz * 16);

    // gx prefetch (epilogue mapping: 3 scalars per thread)
    const float* gxp = g_gx + (size_t)(b0 + bl) * Gsz + j0 + ge;
    const size_t gxstep = (size_t)128 * Gsz;
    float gxr = __ldcg(gxp);
    float gxz = __ldcg(gxp + 256);
    float gxn = __ldcg(gxp + 512);

    int cur = 0;
    for (int t = 0; t < Tsz; ++t) {
        // wait for peers' h(t) stores (all threads acquire-poll)
        if (t > 0) {
            const unsigned* c = cnt + ((t - 1) << 4) + bg;
            unsigned v;
            do {
                asm volatile("ld.acquire.gpu.global.u32 %0, [%1];"
                             : "=r"(v) : "l"(c) : "memory");
            } while (v < 8u);
        }
        // stage h(t) transposed into shT[k][b]
        {
            const float* hsrc = g_hbuf + cur * (Bsz * Hsz) + (b0 << 8);
#pragma unroll
            for (int r = 0; r < 2; ++r) {
                const int i = tid + (r << 8);
                const int bb = i >> 6, k4 = i & 63;
                float4 v = __ldcg((const float4*)(hsrc + (bb << 8)) + k4);
                float* d = shT + (k4 << 2) * 9 + bb;
                d[0] = v.x; d[9] = v.y; d[18] = v.z; d[27] = v.w;
            }
        }
        __syncthreads();

        // GEMM partials: acc[gi][b] over k-chunk kc
        float acc[3][8];
#pragma unroll
        for (int gi = 0; gi < 3; ++gi)
#pragma unroll
            for (int b = 0; b < 8; ++b) acc[gi][b] = 0.0f;

        const float* hk = shT + (kc << 5) * 9;
#pragma unroll
        for (int kk = 0; kk < 32; ++kk) {
            const float* hp = hk + kk * 9;     // warp-uniform address
            float hh[8];
#pragma unroll
            for (int b = 0; b < 8; ++b) hh[b] = hp[b];
#pragma unroll
            for (int gi = 0; gi < 3; ++gi) {
                const float wv = w[gi][kk];
#pragma unroll
                for (int b = 0; b < 8; ++b)
                    acc[gi][b] = fmaf(wv, hh[b], acc[gi][b]);
            }
        }
        // write partials (lane stride 9 -> conflict-free)
#pragma unroll
        for (int gi = 0; gi < 3; ++gi)
#pragma unroll
            for (int b = 0; b < 8; ++b)
                sp[((kc * 96) + gi * 32 + gc) * 9 + b] = acc[gi][b];
        __syncthreads();

        // epilogue: one (b, j) per thread; 8-way k-reduce from sp
        float ar = bhr + gxr, az = bhz + gxz, an = bhn;
#pragma unroll
        for (int k8 = 0; k8 < 8; ++k8) {
            ar += sp[(k8 * 96 + ge) * 9 + bl];
            az += sp[(k8 * 96 + 32 + ge) * 9 + bl];
            an += sp[(k8 * 96 + 64 + ge) * 9 + bl];
        }
        const float r = __fdividef(1.0f, 1.0f + __expf(-ar));
        const float z = __fdividef(1.0f, 1.0f + __expf(-az));
        const float xn = fmaf(r, an, gxn);
        const float e = __expf(2.0f * fabsf(xn));
        float n = 1.0f - __fdividef(2.0f, e + 1.0f);
        n = copysignf(n, xn);

        const float hold = shT[(j0 + ge) * 9 + bl];
        const float hnew = fmaf(z, hold - n, n);   // (1-z)*n + z*h

        __stcg(g_hbuf + (cur ^ 1) * (Bsz * Hsz) + ((b0 + bl) << 8) + j0 + ge, hnew);
        if (write_ys)
            g_h1[(size_t)((t << 7) + b0 + bl) * Hsz + j0 + ge] = hnew;

        // prefetch gx(t+1) (hidden under next step's compute)
        if (t + 1 < Tsz) {
            const float* p = gxp + (size_t)(t + 1) * gxstep;
            gxr = __ldcg(p);
            gxz = __ldcg(p + 256);
            gxn = __ldcg(p + 512);
        }

        __syncthreads();   // all shT/sp reads done, all hnew stores issued
        if (t + 1 < Tsz && tid == 0) {
            // release-arrive: orders the CTA's stores before the increment
            asm volatile("red.release.gpu.global.add.u32 [%0], 1;"
                         :: "l"(cnt + (t << 4) + bg) : "memory");
        }
        cur ^= 1;
    }
}

// ---- head: out[b] = W2 . relu(W1 . h_last[b] + b1) + b2 --------------------
__global__ void head_kernel(const float* __restrict__ W1, const float* __restrict__ b1,
                            const float* __restrict__ W2, const float* __restrict__ b2,
                            float* __restrict__ out)
{
    __shared__ float red[128];
    const int b = blockIdx.x, u = threadIdx.x;
    const float* hb = g_hbuf + (b << 8);    // final h in buffer 0 (T even)
    const float* w  = W1 + (size_t)u * 256;

    float acc = b1[u];
#pragma unroll 8
    for (int k4 = 0; k4 < 64; ++k4) {
        const float4 h4 = __ldcg((const float4*)hb + k4);
        const float4 w4 = __ldg((const float4*)w + k4);
        acc = fmaf(h4.x, w4.x, acc); acc = fmaf(h4.y, w4.y, acc);
        acc = fmaf(h4.z, w4.z, acc); acc = fmaf(h4.w, w4.w, acc);
    }
    red[u] = fmaxf(acc, 0.0f) * __ldg(W2 + u);
    __syncthreads();
#pragma unroll
    for (int s = 64; s > 0; s >>= 1) {
        if (u < s) red[u] += red[u + s];
        __syncthreads();
    }
    if (u == 0) out[b] = red[0] + b2[0];
}

// ---- launch sequence (graph-capturable: kernel launches only) --------------
extern "C" void kernel_launch(void* const* d_in, const int* in_sizes, int n_in,
                              void* d_out, int out_size)
{
    const float* x    = (const float*)d_in[0];
    const float* Wih0 = (const float*)d_in[1];
    const float* Whh0 = (const float*)d_in[2];
    const float* bih0 = (const float*)d_in[3];
    const float* bhh0 = (const float*)d_in[4];
    const float* Wih1 = (const float*)d_in[5];
    const float* Whh1 = (const float*)d_in[6];
    const float* bih1 = (const float*)d_in[7];
    const float* bhh1 = (const float*)d_in[8];
    const float* W1   = (const float*)d_in[9];
    const float* b1   = (const float*)d_in[10];
    const float* W2   = (const float*)d_in[11];
    const float* b2   = (const float*)d_in[12];
    float* out = (float*)d_out;

    const dim3 ggrid(6, 512);

    // fresh state + barrier counters every replay
    zero_state<<<64, 256>>>(1);

    // layer 0
    sgemm_nt<<<ggrid, 256>>>(x, Wih0, bih0, Isz, 0);
    gru_scan<<<128, 256>>>(Whh0, bhh0, 0, 1);

    // layer 1 (re-zero hidden state: layer 1 starts from h=0)
    sgemm_nt<<<ggrid, 256>>>(x, Wih1, bih1, Hsz, 1);
    zero_state<<<64, 256>>>(0);
    gru_scan<<<128, 256>>>(Whh1, bhh1, 1, 0);

    // head
    head_kernel<<<128, 128>>>(W1, b1, W2, b2, out);
}

// round 10
// speedup vs baseline: 2.6514x; 1.0471x over previous
#include <cuda_runtime.h>
#include <cstdint>

#define Bsz 128
#define Tsz 512
#define Isz 64
#define Hsz 256
#define Gsz 768   // 3*H

// ---- device scratch (no cudaMalloc allowed) --------------------------------
__device__ float    g_gx  [(size_t)Tsz * Bsz * Gsz];  // [t][b][768] gate preactivations
__device__ float    g_h1  [(size_t)Tsz * Bsz * Hsz];  // [t][b][256] layer-0 outputs
__device__ float    g_hbuf[2 * Bsz * Hsz];            // double-buffered hidden state
__device__ unsigned g_cnt [2 * Tsz * 16];             // per layer/step/batch-group barrier

// ---- zero hidden state (+ optionally barrier counters) ---------------------
__global__ void zero_state(int zero_cnt) {
    const int stride = gridDim.x * blockDim.x;
    const int i0 = blockIdx.x * blockDim.x + threadIdx.x;
    for (int i = i0; i < 2 * Bsz * Hsz; i += stride) g_hbuf[i] = 0.0f;
    if (zero_cnt)
        for (int i = i0; i < 2 * Tsz * 16; i += stride) g_cnt[i] = 0u;
}

// ---- tf32x3 tensor-core GEMM (NT): g_gx[m][n] = A(m,:)·W(n,:) + bias[n] ----
// mode 0: Arow(m)=x[(b*T+t)*I], m = t*128+b (bm=t, local row=b), K=64
// mode 1: Arow(m)=g_h1+m*256, K=256
// CTA tile 128x64, chunks of K=32; 8 warps (4 m x 2 n), warp tile 32x32.
// Split: v = hi + lo (both tf32-rounded); D = Ah*Bh + Ah*Bl + Al*Bh.
#define GSTRIDE 36
#define GEMM_SMEM_FLOATS (128*GSTRIDE*2 + 64*GSTRIDE*2)
#define GEMM_SMEM_BYTES  (GEMM_SMEM_FLOATS * 4)   // 55296

__device__ __forceinline__ void tf32_split(float v, float& hi, float& lo) {
    unsigned hb, lb;
    asm("cvt.rna.tf32.f32 %0, %1;" : "=r"(hb) : "f"(v));
    float h = __uint_as_float(hb);
    float l = v - h;
    asm("cvt.rna.tf32.f32 %0, %1;" : "=r"(lb) : "f"(l));
    hi = h;
    lo = __uint_as_float(lb);
}

#define MMA_TF32(c, a, b)                                                     \
    asm volatile(                                                             \
        "mma.sync.aligned.m16n8k8.row.col.f32.tf32.tf32.f32 "                 \
        "{%0,%1,%2,%3},{%4,%5,%6,%7},{%8,%9},{%0,%1,%2,%3};"                  \
        : "+f"((c)[0]), "+f"((c)[1]), "+f"((c)[2]), "+f"((c)[3])              \
        : "r"((a)[0]), "r"((a)[1]), "r"((a)[2]), "r"((a)[3]),                 \
          "r"((b)[0]), "r"((b)[1]))

__global__ __launch_bounds__(256) void gemm_tf32(
    const float* __restrict__ A, const float* __restrict__ W,
    const float* __restrict__ bias, int K, int mode)
{
    extern __shared__ float gsm[];
    float* sAh = gsm;                         // [128][36]
    float* sAl = sAh + 128 * GSTRIDE;         // [128][36]
    float* sBh = sAl + 128 * GSTRIDE;         // [64][36]
    float* sBl = sBh + 64 * GSTRIDE;          // [64][36]

    const int tid  = threadIdx.x;
    const int warp = tid >> 5, lane = tid & 31;
    const int gr   = lane >> 2, tg = lane & 3;
    const int wm   = warp & 3,  wn = warp >> 2;
    const int bm   = blockIdx.y, bn = blockIdx.x;   // bn over 12 n-tiles of 64

    float c[2][4][4];
#pragma unroll
    for (int ms = 0; ms < 2; ++ms)
#pragma unroll
        for (int ns = 0; ns < 4; ++ns)
#pragma unroll
            for (int i = 0; i < 4; ++i) c[ms][ns][i] = 0.0f;

    for (int kc = 0; kc < K; kc += 32) {
        __syncthreads();
        // stage A chunk: 128 rows x 32 floats (split hi/lo)
#pragma unroll
        for (int idx = tid; idx < 1024; idx += 256) {
            const int row = idx >> 3, c4 = idx & 7;
            const float* src =
                (mode == 0) ? A    + ((size_t)row * Tsz + bm) * Isz + kc + (c4 << 2)
                            : g_h1 + ((size_t)bm * 128 + row) * Hsz + kc + (c4 << 2);
            float4 v = __ldg((const float4*)src);
            float* dh = sAh + row * GSTRIDE + (c4 << 2);
            float* dl = sAl + row * GSTRIDE + (c4 << 2);
            tf32_split(v.x, dh[0], dl[0]);
            tf32_split(v.y, dh[1], dl[1]);
            tf32_split(v.z, dh[2], dl[2]);
            tf32_split(v.w, dh[3], dl[3]);
        }
        // stage B chunk: 64 rows x 32 floats (split hi/lo)
#pragma unroll
        for (int idx = tid; idx < 512; idx += 256) {
            const int row = idx >> 3, c4 = idx & 7;
            const float* src = W + ((size_t)(bn * 64 + row)) * K + kc + (c4 << 2);
            float4 v = __ldg((const float4*)src);
            float* dh = sBh + row * GSTRIDE + (c4 << 2);
            float* dl = sBl + row * GSTRIDE + (c4 << 2);
            tf32_split(v.x, dh[0], dl[0]);
            tf32_split(v.y, dh[1], dl[1]);
            tf32_split(v.z, dh[2], dl[2]);
            tf32_split(v.w, dh[3], dl[3]);
        }
        __syncthreads();

#pragma unroll
        for (int ks = 0; ks < 4; ++ks) {
            const int k0 = ks << 3;
            unsigned Ah[2][4], Al[2][4];
#pragma unroll
            for (int ms = 0; ms < 2; ++ms) {
                const int r0 = wm * 32 + ms * 16;
                const float* ph = sAh + (r0 + gr) * GSTRIDE + k0 + tg;
                const float* pl = sAl + (r0 + gr) * GSTRIDE + k0 + tg;
                Ah[ms][0] = __float_as_uint(ph[0]);
                Ah[ms][1] = __float_as_uint(ph[8 * GSTRIDE]);
                Ah[ms][2] = __float_as_uint(ph[4]);
                Ah[ms][3] = __float_as_uint(ph[8 * GSTRIDE + 4]);
                Al[ms][0] = __float_as_uint(pl[0]);
                Al[ms][1] = __float_as_uint(pl[8 * GSTRIDE]);
                Al[ms][2] = __float_as_uint(pl[4]);
                Al[ms][3] = __float_as_uint(pl[8 * GSTRIDE + 4]);
            }
            unsigned Bh[4][2], Bl[4][2];
#pragma unroll
            for (int ns = 0; ns < 4; ++ns) {
                const int n0 = wn * 32 + ns * 8;
                const float* ph = sBh + (n0 + gr) * GSTRIDE + k0 + tg;
                const float* pl = sBl + (n0 + gr) * GSTRIDE + k0 + tg;
                Bh[ns][0] = __float_as_uint(ph[0]);
                Bh[ns][1] = __float_as_uint(ph[4]);
                Bl[ns][0] = __float_as_uint(pl[0]);
                Bl[ns][1] = __float_as_uint(pl[4]);
            }
#pragma unroll
            for (int ms = 0; ms < 2; ++ms)
#pragma unroll
                for (int ns = 0; ns < 4; ++ns) {
                    MMA_TF32(c[ms][ns], Ah[ms], Bh[ns]);
                    MMA_TF32(c[ms][ns], Ah[ms], Bl[ns]);
                    MMA_TF32(c[ms][ns], Al[ms], Bh[ns]);
                }
        }
    }

    // epilogue: bias add + store
#pragma unroll
    for (int ms = 0; ms < 2; ++ms) {
#pragma unroll
        for (int ns = 0; ns < 4; ++ns) {
            const int col = bn * 64 + wn * 32 + ns * 8 + tg * 2;
            const float b0 = __ldg(bias + col);
            const float b1 = __ldg(bias + col + 1);
            const size_t m0 = (size_t)bm * 128 + wm * 32 + ms * 16 + gr;
            float2 v0 = make_float2(c[ms][ns][0] + b0, c[ms][ns][1] + b1);
            float2 v1 = make_float2(c[ms][ns][2] + b0, c[ms][ns][3] + b1);
            *(float2*)(g_gx + m0 * Gsz + col)       = v0;
            *(float2*)(g_gx + (m0 + 8) * Gsz + col) = v1;
        }
    }
}

// ---- persistent GRU scan (unchanged from R9) --------------------------------
__global__ __launch_bounds__(256, 1) void gru_scan(
    const float* __restrict__ Whh, const float* __restrict__ bhh,
    int layer, int write_ys)
{
    __shared__ float shT[256 * 9];      // h transposed: [k][b], row pad 9
    __shared__ float sp [8 * 96 * 9];   // partials: [kc][g(96)][b], row pad 9

    const int tid = threadIdx.x;
    const int bg  = blockIdx.x >> 3;    // 0..15
    const int hg  = blockIdx.x & 7;     // 0..7
    const int b0  = bg << 3, j0 = hg << 5;

    const int kc = tid >> 5;            // k-chunk 0..7
    const int gc = tid & 31;            // hidden unit 0..31
    const int bl = tid >> 5;            // epilogue batch 0..7
    const int ge = tid & 31;            // epilogue hidden unit

    float w[3][32];
#pragma unroll
    for (int gi = 0; gi < 3; ++gi) {
        const float* wrow = Whh + (size_t)(gi * 256 + j0 + gc) * 256 + (kc << 5);
#pragma unroll
        for (int q = 0; q < 8; ++q) {
            float4 v = __ldg((const float4*)wrow + q);
            w[gi][q*4+0] = v.x; w[gi][q*4+1] = v.y;
            w[gi][q*4+2] = v.z; w[gi][q*4+3] = v.w;
        }
    }
    const float bhr = bhh[j0 + ge];
    const float bhz = bhh[256 + j0 + ge];
    const float bhn = bhh[512 + j0 + ge];
    unsigned* cnt = g_cnt + layer * (Tsz * 16);

    const float* gxp = g_gx + (size_t)(b0 + bl) * Gsz + j0 + ge;
    const size_t gxstep = (size_t)128 * Gsz;
    float gxr = __ldcg(gxp);
    float gxz = __ldcg(gxp + 256);
    float gxn = __ldcg(gxp + 512);

    int cur = 0;
    for (int t = 0; t < Tsz; ++t) {
        if (t > 0) {
            const unsigned* c = cnt + ((t - 1) << 4) + bg;
            unsigned v;
            do {
                asm volatile("ld.acquire.gpu.global.u32 %0, [%1];"
                             : "=r"(v) : "l"(c) : "memory");
            } while (v < 8u);
        }
        {
            const float* hsrc = g_hbuf + cur * (Bsz * Hsz) + (b0 << 8);
#pragma unroll
            for (int r = 0; r < 2; ++r) {
                const int i = tid + (r << 8);
                const int bb = i >> 6, k4 = i & 63;
                float4 v = __ldcg((const float4*)(hsrc + (bb << 8)) + k4);
                float* d = shT + (k4 << 2) * 9 + bb;
                d[0] = v.x; d[9] = v.y; d[18] = v.z; d[27] = v.w;
            }
        }
        __syncthreads();

        float acc[3][8];
#pragma unroll
        for (int gi = 0; gi < 3; ++gi)
#pragma unroll
            for (int b = 0; b < 8; ++b) acc[gi][b] = 0.0f;

        const float* hk = shT + (kc << 5) * 9;
#pragma unroll
        for (int kk = 0; kk < 32; ++kk) {
            const float* hp = hk + kk * 9;
            float hh[8];
#pragma unroll
            for (int b = 0; b < 8; ++b) hh[b] = hp[b];
#pragma unroll
            for (int gi = 0; gi < 3; ++gi) {
                const float wv = w[gi][kk];
#pragma unroll
                for (int b = 0; b < 8; ++b)
                    acc[gi][b] = fmaf(wv, hh[b], acc[gi][b]);
            }
        }
#pragma unroll
        for (int gi = 0; gi < 3; ++gi)
#pragma unroll
            for (int b = 0; b < 8; ++b)
                sp[((kc * 96) + gi * 32 + gc) * 9 + b] = acc[gi][b];
        __syncthreads();

        float ar = bhr + gxr, az = bhz + gxz, an = bhn;
#pragma unroll
        for (int k8 = 0; k8 < 8; ++k8) {
            ar += sp[(k8 * 96 + ge) * 9 + bl];
            az += sp[(k8 * 96 + 32 + ge) * 9 + bl];
            an += sp[(k8 * 96 + 64 + ge) * 9 + bl];
        }
        const float r = __fdividef(1.0f, 1.0f + __expf(-ar));
        const float z = __fdividef(1.0f, 1.0f + __expf(-az));
        const float xn = fmaf(r, an, gxn);
        const float e = __expf(2.0f * fabsf(xn));
        float n = 1.0f - __fdividef(2.0f, e + 1.0f);
        n = copysignf(n, xn);

        const float hold = shT[(j0 + ge) * 9 + bl];
        const float hnew = fmaf(z, hold - n, n);

        __stcg(g_hbuf + (cur ^ 1) * (Bsz * Hsz) + ((b0 + bl) << 8) + j0 + ge, hnew);
        if (write_ys)
            g_h1[(size_t)((t << 7) + b0 + bl) * Hsz + j0 + ge] = hnew;

        if (t + 1 < Tsz) {
            const float* p = gxp + (size_t)(t + 1) * gxstep;
            gxr = __ldcg(p);
            gxz = __ldcg(p + 256);
            gxn = __ldcg(p + 512);
        }

        __syncthreads();
        if (t + 1 < Tsz && tid == 0) {
            asm volatile("red.release.gpu.global.add.u32 [%0], 1;"
                         :: "l"(cnt + (t << 4) + bg) : "memory");
        }
        cur ^= 1;
    }
}

// ---- head: out[b] = W2 . relu(W1 . h_last[b] + b1) + b2 --------------------
__global__ void head_kernel(const float* __restrict__ W1, const float* __restrict__ b1,
                            const float* __restrict__ W2, const float* __restrict__ b2,
                            float* __restrict__ out)
{
    __shared__ float red[128];
    const int b = blockIdx.x, u = threadIdx.x;
    const float* hb = g_hbuf + (b << 8);
    const float* w  = W1 + (size_t)u * 256;

    float acc = b1[u];
#pragma unroll 8
    for (int k4 = 0; k4 < 64; ++k4) {
        const float4 h4 = __ldcg((const float4*)hb + k4);
        const float4 w4 = __ldg((const float4*)w + k4);
        acc = fmaf(h4.x, w4.x, acc); acc = fmaf(h4.y, w4.y, acc);
        acc = fmaf(h4.z, w4.z, acc); acc = fmaf(h4.w, w4.w, acc);
    }
    red[u] = fmaxf(acc, 0.0f) * __ldg(W2 + u);
    __syncthreads();
#pragma unroll
    for (int s = 64; s > 0; s >>= 1) {
        if (u < s) red[u] += red[u + s];
        __syncthreads();
    }
    if (u == 0) out[b] = red[0] + b2[0];
}

// ---- launch sequence (graph-capturable: kernel launches only) --------------
extern "C" void kernel_launch(void* const* d_in, const int* in_sizes, int n_in,
                              void* d_out, int out_size)
{
    const float* x    = (const float*)d_in[0];
    const float* Wih0 = (const float*)d_in[1];
    const float* Whh0 = (const float*)d_in[2];
    const float* bih0 = (const float*)d_in[3];
    const float* bhh0 = (const float*)d_in[4];
    const float* Wih1 = (const float*)d_in[5];
    const float* Whh1 = (const float*)d_in[6];
    const float* bih1 = (const float*)d_in[7];
    const float* bhh1 = (const float*)d_in[8];
    const float* W1   = (const float*)d_in[9];
    const float* b1   = (const float*)d_in[10];
    const float* W2   = (const float*)d_in[11];
    const float* b2   = (const float*)d_in[12];
    float* out = (float*)d_out;

    cudaFuncSetAttribute(gemm_tf32, cudaFuncAttributeMaxDynamicSharedMemorySize,
                         GEMM_SMEM_BYTES);

    const dim3 ggrid(12, 512);   // 12 n-tiles of 64, 512 t-tiles of 128 rows

    // fresh state + barrier counters every replay
    zero_state<<<64, 256>>>(1);

    // layer 0
    gemm_tf32<<<ggrid, 256, GEMM_SMEM_BYTES>>>(x, Wih0, bih0, Isz, 0);
    gru_scan<<<128, 256>>>(Whh0, bhh0, 0, 1);

    // layer 1 (re-zero hidden state: layer 1 starts from h=0)
    gemm_tf32<<<ggrid, 256, GEMM_SMEM_BYTES>>>(x, Wih1, bih1, Hsz, 1);
    zero_state<<<64, 256>>>(0);
    gru_scan<<<128, 256>>>(Whh1, bhh1, 1, 0);

    // head
    head_kernel<<<128, 128>>>(W1, b1, W2, b2, out);
}